// round 17
// baseline (speedup 1.0000x reference)
#include <cuda_runtime.h>
#include <cuda_bf16.h>
#include <math_constants.h>
#include <math.h>

#define CDIM     64
#define NCODES   1024
#define KTOT     2048
#define BATCH    32
#define N_VEC    (BATCH * KTOT)          // 65536
#define Z_ELEMS  (BATCH * CDIM * KTOT)   // 4194304
#define MTILE    128
#define NKS      4                       // K=64: A=[zh], B=[eh]
#define CHUNKC   64
#define NPAIRS   8
#define NTHREADS 512
#define NGRID    256                     // 2 tiles per CTA, 2 CTAs/SM
#define APITCH   72
#define BPITCH   72

// smem layout (bytes)
#define ZS_B     0                        // persistent fp32 z tile 64x128 = 32768
#define A_B      32768                    // A halves 128x72x2 = 18432 -> 51200
#define B0_B     51200                    // 2 pair-bufs x 18432 = 36864 -> 88064
#define EES_B    88064                    // 2 x 512 = 1024
#define ZZS_B    89088                    // 128 floats
#define SLS_B    89600                    // 16 doubles
#define FLG_B    89728                    // flag int (+pad)
#define RED_B    89792                    // finalize: 512 f + 512 d = 6144
#define SMEM_BYTES 95936

// post-mainloop reuse:
#define MGP_B    A_B                      // u32 [8][128] = 4096
#define CAND_B   (A_B + 4096)             // int [4][128] = 2048
#define RFND_B   (A_B + 6144)             // float [4][128] = 2048
#define RFNI_B   (A_B + 8192)             // int [4][128] = 2048
#define STQ_B    B0_B                     // staging 32768 (fits in 36864)

#define PAIR_U4  1152                    // 2 chunks x 576 uint4

__device__ float  g_ee[NCODES];          // exact norms (refine)
__device__ float  g_eeq[NCODES];         // ee + 0.25 (screen positivity offset)
__device__ int    g_hist[NCODES];
__device__ double g_loss_part[NGRID];
__device__ int    g_count = 0;
__device__ __align__(16) unsigned short g_bh[NCODES * BPITCH];   // [eh] codebook

// ---------------------------------------------------------------------------
__device__ __forceinline__ unsigned smem_u32(const void* p) {
    unsigned a;
    asm("{ .reg .u64 t; cvta.to.shared.u64 t, %1; cvt.u32.u64 %0, t; }"
        : "=r"(a) : "l"(p));
    return a;
}
__device__ __forceinline__ void ldsm4(unsigned& r0, unsigned& r1, unsigned& r2,
                                      unsigned& r3, unsigned addr) {
    asm volatile("ldmatrix.sync.aligned.m8n8.x4.shared.b16 {%0,%1,%2,%3}, [%4];"
                 : "=r"(r0), "=r"(r1), "=r"(r2), "=r"(r3) : "r"(addr));
}
__device__ __forceinline__ void mma16816(float* c, unsigned a0, unsigned a1,
                                         unsigned a2, unsigned a3,
                                         unsigned b0, unsigned b1) {
    asm volatile(
        "mma.sync.aligned.m16n8k16.row.col.f32.bf16.bf16.f32 "
        "{%0,%1,%2,%3}, {%4,%5,%6,%7}, {%8,%9}, {%0,%1,%2,%3};"
        : "+f"(c[0]), "+f"(c[1]), "+f"(c[2]), "+f"(c[3])
        : "r"(a0), "r"(a1), "r"(a2), "r"(a3), "r"(b0), "r"(b1));
}
__device__ __forceinline__ void cpa16(unsigned dst, const void* src) {
    asm volatile("cp.async.cg.shared.global [%0], [%1], 16;"
                 :: "r"(dst), "l"(src));
}
__device__ __forceinline__ void cpa4(unsigned dst, const void* src) {
    asm volatile("cp.async.ca.shared.global [%0], [%1], 4;"
                 :: "r"(dst), "l"(src));
}
__device__ __forceinline__ void cpa_commit() {
    asm volatile("cp.async.commit_group;" ::: "memory");
}
template <int N>
__device__ __forceinline__ void cpa_wait() {
    asm volatile("cp.async.wait_group %0;" :: "n"(N) : "memory");
}
__device__ __forceinline__ bool better(float da, int ia, float db, int ib) {
    return da < db || (da == db && ia < ib);
}

// ---------------------------------------------------------------------------
// prep: code norms (ascending-c), [eh] codebook image, zero hist
// ---------------------------------------------------------------------------
__global__ void vq_prep(const float* __restrict__ cb) {
    int j = blockIdx.x * blockDim.x + threadIdx.x;
    if (j >= NCODES) return;
    const float4* row4 = (const float4*)(cb + j * CDIM);
    float r[CDIM];
#pragma unroll
    for (int q = 0; q < CDIM / 4; ++q) {
        float4 v = __ldg(&row4[q]);
        r[q * 4 + 0] = v.x; r[q * 4 + 1] = v.y;
        r[q * 4 + 2] = v.z; r[q * 4 + 3] = v.w;
    }
    unsigned short* img = g_bh + j * BPITCH;
    float s = 0.f;
#pragma unroll
    for (int c = 0; c < CDIM; ++c) {
        float e = r[c];
        s = __fadd_rn(s, __fmul_rn(e, e));
        img[c] = __bfloat16_as_ushort(__float2bfloat16(e));
    }
#pragma unroll
    for (int c = CDIM; c < BPITCH; ++c) img[c] = 0;
    g_ee[j]   = s;
    g_eeq[j]  = s + 0.25f;
    g_hist[j] = 0;
}

// ---------------------------------------------------------------------------
// main: 2-tile persistent CTAs; persistent smem z (cp.async); pair-granular
//       chunks w/ double buffer; K=64 HMMA positive-packed screen;
//       exact fp32 refine from resident z. grid=256, block=512.
// ---------------------------------------------------------------------------
__global__ __launch_bounds__(NTHREADS, 2)
void vq_main(const float* __restrict__ z_e, const float* __restrict__ cb,
             float* __restrict__ out) {
    extern __shared__ char sm[];
    float*  zs  = (float*)(sm + ZS_B);
    float*  zzs = (float*)(sm + ZZS_B);
    double* sls = (double*)(sm + SLS_B);
    int*    flg = (int*)(sm + FLG_B);
    const unsigned smem_base = smem_u32(sm);

    const int tid  = threadIdx.x;
    const int lane = tid & 31;
    const int w    = tid >> 5;
    const int rg   = w & 3;
    const int cg   = w >> 2;
    const int lrow = (lane & 7) + ((lane >> 3) & 1) * 8;
    const int lkof = (lane >> 4) * 8;
    const unsigned a_base =
        smem_base + A_B + (unsigned)((rg * 32 + lrow) * APITCH + lkof) * 2;
    const unsigned b_row = (unsigned)((cg * 16 + lrow) * BPITCH + lkof) * 2;

    double loss_acc = 0.0;

    for (int t = 0; t < 2; ++t) {
        const int tile = blockIdx.x * 2 + t;
        const int b    = tile >> 4;
        const int k0v  = (tile & 15) * MTILE;
        const float* zbase = z_e + ((size_t)b * CDIM) * KTOT + k0v;

        // --- group 1: z tile fp32 into smem (persistent for the tile) ---
#pragma unroll
        for (int i = 0; i < 4; ++i) {
            int idx4 = tid + i * NTHREADS;       // 0..2047
            int c = idx4 >> 5, v4 = idx4 & 31;
            cpa16(smem_base + ZS_B + (unsigned)(c * MTILE + v4 * 4) * 4,
                  zbase + (size_t)c * KTOT + v4 * 4);
        }
        cpa_commit();

        // --- group 2: B pair 0 into slot 0 ---
        {
            const uint4* src = (const uint4*)g_bh;
#pragma unroll
            for (int i = 0; i < 3; ++i) {
                int idx = tid + i * NTHREADS;
                if (idx < PAIR_U4) cpa16(smem_base + B0_B + idx * 16, src + idx);
            }
            if (tid < 128) cpa4(smem_base + EES_B + tid * 4, &g_eeq[tid]);
            cpa_commit();
        }
        cpa_wait<1>();     // z done (B pair 0 may still be in flight)
        __syncthreads();

        // --- A=[zh] image from smem z (all 512 threads, 4 per row) ---
        {
            const int m   = tid & 127;
            const int seg = tid >> 7;            // 16 dims each
            unsigned short* arow = (unsigned short*)(sm + A_B) + m * APITCH;
#pragma unroll
            for (int c16 = 0; c16 < 16; ++c16) {
                int c = seg * 16 + c16;
                arow[c] = __bfloat16_as_ushort(__float2bfloat16(zs[c * MTILE + m]));
            }
        }
        // --- per-vector norm (ascending-c sequential; bit-exact) ---
        if (tid < MTILE) {
            const int m = tid;
            float s = 0.f;
#pragma unroll
            for (int c = 0; c < CDIM; ++c) {
                float z = zs[c * MTILE + m];
                s = __fadd_rn(s, __fmul_rn(z, z));
            }
            zzs[m] = s;
        }
        __syncthreads();

        unsigned t1[4], t2[4];
#pragma unroll
        for (int ri = 0; ri < 4; ++ri) { t1[ri] = 0xFFFFFFFFu; t2[ri] = 0xFFFFFFFFu; }

        for (int p = 0; p < NPAIRS; ++p) {
            // prefetch pair p+1 into slot (p+1)%2 (double buffer)
            if (p < NPAIRS - 1) {
                const uint4* src =
                    (const uint4*)(g_bh + (size_t)(p + 1) * 2 * CHUNKC * BPITCH);
                unsigned dstb = smem_base + B0_B + ((p + 1) & 1) * 18432;
                unsigned dste = smem_base + EES_B + ((p + 1) & 1) * 512;
#pragma unroll
                for (int i = 0; i < 3; ++i) {
                    int idx = tid + i * NTHREADS;
                    if (idx < PAIR_U4) cpa16(dstb + idx * 16, src + idx);
                }
                if (tid < 128) cpa4(dste + tid * 4, &g_eeq[(p + 1) * 128 + tid]);
                cpa_commit();
                cpa_wait<1>();     // pair p complete
            } else {
                cpa_wait<0>();
            }
            __syncthreads();       // pair p visible to all warps

#pragma unroll
            for (int cc = 0; cc < 2; ++cc) {
                const int chunk = p * 2 + cc;
                const unsigned b_base =
                    smem_base + B0_B + (p & 1) * 18432 + cc * 9216 + b_row;
                const float* ees =
                    (const float*)(sm + EES_B + (p & 1) * 512 + cc * 256);

                float acc[2][2][4];
#pragma unroll
                for (int rf = 0; rf < 2; ++rf)
#pragma unroll
                    for (int j = 0; j < 2; ++j)
#pragma unroll
                        for (int r = 0; r < 4; ++r) acc[rf][j][r] = 0.f;

#pragma unroll
                for (int s = 0; s < NKS; ++s) {
                    unsigned a0, a1, a2, a3, e0, e1, e2, e3, b0, b1, b2, b3;
                    ldsm4(a0, a1, a2, a3, a_base + (unsigned)(s * 16) * 2);
                    ldsm4(e0, e1, e2, e3, a_base + (unsigned)(16 * APITCH + s * 16) * 2);
                    ldsm4(b0, b1, b2, b3, b_base + (unsigned)(s * 16) * 2);
                    mma16816(acc[0][0], a0, a1, a2, a3, b0, b2);
                    mma16816(acc[0][1], a0, a1, a2, a3, b1, b3);
                    mma16816(acc[1][0], e0, e1, e2, e3, b0, b2);
                    mma16816(acc[1][1], e0, e1, e2, e3, b1, b3);
                }

                // screen: d = (ee+0.25) - 2*(zh.eh) > 0; raw-bit packed top-2
#pragma unroll
                for (int j = 0; j < 2; ++j) {
                    int e0i = cg * 16 + j * 8 + (lane & 3) * 2;
                    unsigned cg0 = (unsigned)(chunk * CHUNKC + e0i);
                    float ee0 = ees[e0i], ee1 = ees[e0i + 1];
#pragma unroll
                    for (int rf = 0; rf < 2; ++rf) {
#pragma unroll
                        for (int r = 0; r < 4; ++r) {
                            float ee = (r & 1) ? ee1 : ee0;
                            unsigned idx = cg0 + (unsigned)(r & 1);
                            int ri = rf * 2 + (r >> 1);
                            float dp = fmaf(-2.0f, acc[rf][j][r], ee);
                            unsigned pk = (__float_as_uint(dp) & 0xFFFFFC00u) | idx;
                            unsigned hi = max(pk, t1[ri]);
                            t1[ri] = min(pk, t1[ri]);
                            t2[ri] = min(t2[ri], hi);
                        }
                    }
                }
            }
            __syncthreads();       // double buffer: slot consumed before reuse
        }

        // --- merge top-2 across the quad ---
#pragma unroll
        for (int xm = 1; xm <= 2; xm <<= 1) {
#pragma unroll
            for (int ri = 0; ri < 4; ++ri) {
                unsigned o1 = __shfl_xor_sync(0xffffffffu, t1[ri], xm);
                unsigned o2 = __shfl_xor_sync(0xffffffffu, t2[ri], xm);
                unsigned lo = min(t1[ri], o1);
                unsigned hi = max(t1[ri], o1);
                t2[ri] = min(hi, min(t2[ri], o2));
                t1[ri] = lo;
            }
        }

        unsigned* mgp = (unsigned*)(sm + MGP_B);   // A region dead
        if ((lane & 3) == 0) {
#pragma unroll
            for (int ri = 0; ri < 4; ++ri) {
                int row = rg * 32 + (ri >> 1) * 16 + (ri & 1) * 8 + (lane >> 2);
                mgp[(cg * 2 + 0) * MTILE + row] = t1[ri];
                mgp[(cg * 2 + 1) * MTILE + row] = t2[ri];
            }
        }
        __syncthreads();

        // --- select global top-4 of 8 packed values ---
        int* cand = (int*)(sm + CAND_B);
        if (tid < MTILE) {
            const int m = tid;
            unsigned pp[8];
#pragma unroll
            for (int q = 0; q < 8; ++q) pp[q] = mgp[q * MTILE + m];
#pragma unroll
            for (int k = 0; k < 4; ++k) {
                int bj = k;
#pragma unroll
                for (int j = k + 1; j < 8; ++j)
                    if (pp[j] < pp[bj]) bj = j;
                unsigned tt = pp[k]; pp[k] = pp[bj]; pp[bj] = tt;
                cand[k * MTILE + m] = (int)(pp[k] & 1023u);
            }
        }
        __syncthreads();

        // --- parallel exact fp32 refine: 4 threads per vector, z resident ---
        float* rfnd = (float*)(sm + RFND_B);
        int*   rfni = (int*)(sm + RFNI_B);
        {
            const int q  = tid >> 7;
            const int m2 = tid & 127;
            int ci = cand[q * MTILE + m2];
            float zz2 = zzs[m2];
            const float4* crow = (const float4*)(cb + (size_t)ci * CDIM);
            float a = 0.f;
#pragma unroll
            for (int c4 = 0; c4 < CDIM / 4; ++c4) {
                float4 qv = __ldg(&crow[c4]);
                a = fmaf(zs[(c4 * 4 + 0) * MTILE + m2], qv.x, a);
                a = fmaf(zs[(c4 * 4 + 1) * MTILE + m2], qv.y, a);
                a = fmaf(zs[(c4 * 4 + 2) * MTILE + m2], qv.z, a);
                a = fmaf(zs[(c4 * 4 + 3) * MTILE + m2], qv.w, a);
            }
            rfnd[q * MTILE + m2] = fmaf(-2.0f, a, __fadd_rn(zz2, __ldg(&g_ee[ci])));
            rfni[q * MTILE + m2] = ci;
        }
        __syncthreads();

        // --- final select + outputs ---
        float* stq = (float*)(sm + STQ_B);   // B region dead
        if (tid < MTILE) {
            const int m = tid;
            float bd = rfnd[m]; int bidx = rfni[m];
#pragma unroll
            for (int q = 1; q < 4; ++q) {
                float d = rfnd[q * MTILE + m];
                int   x = rfni[q * MTILE + m];
                if (better(d, x, bd, bidx)) { bd = d; bidx = x; }
            }

            out[Z_ELEMS + (size_t)b * KTOT + k0v + m] = (float)bidx;
            atomicAdd(&g_hist[bidx], 1);

            const float4* crow = (const float4*)(cb + (size_t)bidx * CDIM);
            double lsum = 0.0;
#pragma unroll
            for (int c4 = 0; c4 < CDIM / 4; ++c4) {
                float4 q = __ldg(&crow[c4]);
                float zq[4] = {q.x, q.y, q.z, q.w};
#pragma unroll
                for (int u = 0; u < 4; ++u) {
                    int c = c4 * 4 + u;
                    float ze = zs[c * MTILE + m];
                    float tt = __fsub_rn(zq[u], ze);
                    stq[c * MTILE + m] = __fadd_rn(ze, tt);
                    lsum += (double)__fmul_rn(tt, tt);
                }
            }
#pragma unroll
            for (int o = 16; o > 0; o >>= 1)
                lsum += __shfl_down_sync(0xffffffffu, lsum, o);
            if ((tid & 31) == 0) sls[tid >> 5] = lsum;
        }
        __syncthreads();
        if (tid == 0) loss_acc += sls[0] + sls[1] + sls[2] + sls[3];

        // --- coalesced z_q_st store ---
        {
            float* ob = out + ((size_t)b * CDIM) * KTOT + k0v;
#pragma unroll
            for (int i = 0; i < 4; ++i) {
                int idx4 = tid + i * NTHREADS;
                int c = idx4 >> 5, v4 = idx4 & 31;
                *(float4*)(ob + (size_t)c * KTOT + v4 * 4) =
                    *(const float4*)&stq[c * MTILE + v4 * 4];
            }
        }
        __syncthreads();   // all regions consumed before next tile reuses them
    }

    if (tid == 0) g_loss_part[blockIdx.x] = loss_acc;

    // --- fused finalize: last CTA reduces hist + loss ---
    __threadfence();
    if (tid == 0) {
        int old = atomicAdd(&g_count, 1);
        *flg = (old == NGRID - 1) ? 1 : 0;
    }
    __syncthreads();
    if (*flg) {
        __threadfence();
        float*  red_f = (float*)(sm + RED_B);
        double* red_d = (double*)(sm + RED_B + 2048);
        float ent = 0.f;
#pragma unroll
        for (int i = 0; i < NCODES / NTHREADS; ++i) {
            float p = (float)g_hist[tid + i * NTHREADS] * (1.0f / (float)N_VEC);
            ent += p * logf(p + 1e-10f);
        }
        red_f[tid] = ent;
        red_d[tid] = (tid < NGRID) ? g_loss_part[tid] : 0.0;
        __syncthreads();
        for (int s = 256; s > 0; s >>= 1) {
            if (tid < s) { red_f[tid] += red_f[tid + s]; red_d[tid] += red_d[tid + s]; }
            __syncthreads();
        }
        if (tid == 0) {
            out[Z_ELEMS + N_VEC]     = (float)(red_d[0] * (1.25 / (double)Z_ELEMS));
            out[Z_ELEMS + N_VEC + 1] = expf(-red_f[0]);
            g_count = 0;   // reset for next graph replay
        }
    }
}

// ---------------------------------------------------------------------------
extern "C" void kernel_launch(void* const* d_in, const int* in_sizes, int n_in,
                              void* d_out, int out_size) {
    const float* z_e = (const float*)d_in[0];
    const float* cb  = (const float*)d_in[1];
    float* out = (float*)d_out;

    cudaFuncSetAttribute(vq_main, cudaFuncAttributeMaxDynamicSharedMemorySize,
                         SMEM_BYTES);

    vq_prep<<<8, 128>>>(cb);
    vq_main<<<NGRID, NTHREADS, SMEM_BYTES>>>(z_e, cb, out);
}